// round 3
// baseline (speedup 1.0000x reference)
#include <cuda_runtime.h>
#include <cuda_bf16.h>

#define N_NODES 100000
#define N_EDGES 1200000
#define DIM 64

// Scratch (cudaMalloc is forbidden): aggregation buffer + degree counts.
__device__ float g_agg[(size_t)N_NODES * DIM];
__device__ float g_deg[N_NODES];
__device__ int   g_idx64;   // 1 if edge_index is int64, 0 if int32

// ---------------------------------------------------------------------------
// Kernel 0: detect edge_index dtype. If int64 with values < 2^31, every
// odd-indexed 32-bit word is the zero high-half. 128 random int32 indices
// all having zero odd words is impossible, so this is unambiguous.
// ---------------------------------------------------------------------------
__global__ void detect_kernel(const int* __restrict__ ei32) {
    int nz_odd = 0;
    for (int k = 0; k < 128; k++) nz_odd += (ei32[2 * k + 1] != 0);
    g_idx64 = (nz_odd == 0) ? 1 : 0;
}

// ---------------------------------------------------------------------------
// Kernel 1: zero the scratch buffers.
// ---------------------------------------------------------------------------
__global__ void zero_kernel() {
    const int stride = gridDim.x * blockDim.x;
    int t = blockIdx.x * blockDim.x + threadIdx.x;
    float4* agg4 = reinterpret_cast<float4*>(g_agg);
    const int total4 = N_NODES * DIM / 4;  // 1.6M
    for (int i = t; i < total4; i += stride)
        agg4[i] = make_float4(0.f, 0.f, 0.f, 0.f);
    for (int i = t; i < N_NODES; i += stride)
        g_deg[i] = 0.f;
}

// ---------------------------------------------------------------------------
// Kernel 2: edge scatter. 16 threads per edge; each thread moves one float4
// of the source row via a vector reduction atomic (sm_90+).
// ---------------------------------------------------------------------------
__global__ void edge_kernel(const float* __restrict__ x,
                            const void* __restrict__ ei_raw) {
    long long t = (long long)blockIdx.x * blockDim.x + threadIdx.x;
    int e = (int)(t >> 4);
    int c = (int)(t & 15);
    if (e >= N_EDGES) return;

    long long i, j;
    if (g_idx64) {
        const long long* ei = (const long long*)ei_raw;
        i = ei[e];
        j = ei[N_EDGES + e];
    } else {
        const int* ei = (const int*)ei_raw;
        i = ei[e];
        j = ei[N_EDGES + e];
    }

    const float4* xr = reinterpret_cast<const float4*>(x + j * DIM);
    float4 v = xr[c];
    float* dst = g_agg + i * DIM + c * 4;
    asm volatile("red.global.add.v4.f32 [%0], {%1, %2, %3, %4};"
                 :: "l"(dst), "f"(v.x), "f"(v.y), "f"(v.z), "f"(v.w)
                 : "memory");
    if (c == 0) {
        atomicAdd(g_deg + i, 1.0f);
    }
}

// ---------------------------------------------------------------------------
// Kernel 3: per-node concat-linear + ReLU + LayerNorm.
// One warp per node. W^T cached in shared (conflict-free float2 reads).
// Lane handles output columns (2*lane, 2*lane+1).
// ---------------------------------------------------------------------------
#define NODE_WARPS 8
#define NODE_THREADS (NODE_WARPS * 32)

__global__ void node_kernel(const float* __restrict__ x,
                            const float* __restrict__ W,      // [64][128]
                            const float* __restrict__ bias,   // [64]
                            const float* __restrict__ gamma,  // [64]
                            const float* __restrict__ beta,   // [64]
                            float* __restrict__ out) {
    __shared__ float Wt[2 * DIM * DIM];          // Wt[k*64 + c] = W[c*128 + k]
    __shared__ float stage[NODE_WARPS][2 * DIM]; // concat row per warp

    const int tid = threadIdx.x;
    for (int g = tid; g < DIM * 2 * DIM; g += NODE_THREADS) {
        int c = g >> 7;       // output column 0..63
        int k = g & 127;      // input index  0..127
        Wt[k * DIM + c] = W[g];
    }
    __syncthreads();

    const int warp = tid >> 5;
    const int lane = tid & 31;
    const int c0 = 2 * lane;

    const float b0 = bias[c0],  b1 = bias[c0 + 1];
    const float ga0 = gamma[c0], ga1 = gamma[c0 + 1];
    const float be0 = beta[c0],  be1 = beta[c0 + 1];

    const float2* Wt2 = reinterpret_cast<const float2*>(Wt);
    float2* st = reinterpret_cast<float2*>(stage[warp]);

    const int nodesPerIter = gridDim.x * NODE_WARPS;
    for (int node = blockIdx.x * NODE_WARPS + warp; node < N_NODES;
         node += nodesPerIter) {
        // Stage concat row: [ x(64) | agg/deg(64) ]
        const float2* xr = reinterpret_cast<const float2*>(x + (size_t)node * DIM);
        const float2* ar = reinterpret_cast<const float2*>(g_agg + (size_t)node * DIM);
        float2 xv = xr[lane];
        float2 av = ar[lane];
        float deg = g_deg[node];
        float inv = 1.0f / fmaxf(deg, 1.0f);
        st[lane]      = xv;
        st[32 + lane] = make_float2(av.x * inv, av.y * inv);
        __syncwarp();

        // GEMV: two adjacent output columns per lane.
        float acc0 = b0, acc1 = b1;
        const float* row = stage[warp];
        #pragma unroll 8
        for (int k = 0; k < 2 * DIM; k++) {
            float in = row[k];                // broadcast LDS
            float2 w = Wt2[k * 32 + lane];    // conflict-free LDS.64
            acc0 += in * w.x;
            acc1 += in * w.y;
        }

        float h0 = fmaxf(acc0, 0.f);
        float h1 = fmaxf(acc1, 0.f);

        // LayerNorm over the 64 outputs held by this warp (2 per lane).
        float s  = h0 + h1;
        float sq = h0 * h0 + h1 * h1;
        #pragma unroll
        for (int o = 16; o > 0; o >>= 1) {
            s  += __shfl_xor_sync(0xFFFFFFFFu, s,  o);
            sq += __shfl_xor_sync(0xFFFFFFFFu, sq, o);
        }
        const float mu  = s * (1.0f / DIM);
        const float var = sq * (1.0f / DIM) - mu * mu;
        const float rstd = rsqrtf(var + 1e-5f);

        float2 o2;
        o2.x = (h0 - mu) * rstd * ga0 + be0;
        o2.y = (h1 - mu) * rstd * ga1 + be1;
        reinterpret_cast<float2*>(out + (size_t)node * DIM)[lane] = o2;
        __syncwarp();  // protect stage before next iteration overwrites it
    }
}

// ---------------------------------------------------------------------------
extern "C" void kernel_launch(void* const* d_in, const int* in_sizes, int n_in,
                              void* d_out, int out_size) {
    const float* x          = (const float*)d_in[0];   // [100000, 64]
    const float* W          = (const float*)d_in[1];   // [64, 128]
    const float* bias       = (const float*)d_in[2];   // [64]
    const float* gamma      = (const float*)d_in[3];   // [64]
    const float* beta       = (const float*)d_in[4];   // [64]
    const void*  ei         = d_in[5];                 // [2, 1200000] int32 or int64
    float* out              = (float*)d_out;

    // 0) dtype detection for edge_index
    detect_kernel<<<1, 1>>>((const int*)ei);

    // 1) zero scratch
    zero_kernel<<<4096, 256>>>();

    // 2) edge scatter: 16 threads per edge
    {
        long long threads = (long long)N_EDGES * 16;
        int blocks = (int)((threads + 255) / 256);
        edge_kernel<<<blocks, 256>>>(x, ei);
    }

    // 3) node phase: persistent warps, one warp per node
    node_kernel<<<148 * 4, NODE_THREADS>>>(x, W, bias, gamma, beta, out);
}

// round 4
// speedup vs baseline: 1.4216x; 1.4216x over previous
#include <cuda_runtime.h>
#include <cuda_bf16.h>

#define N_NODES 100000
#define N_EDGES 1200000
#define DIM 64

// Scratch (cudaMalloc is forbidden).
__device__ float g_agg[(size_t)N_NODES * DIM];
__device__ float g_deg[N_NODES];
__device__ int   g_idx64;   // 1 if edge_index is int64, 0 if int32

// ---------------------------------------------------------------------------
// f32x2 packed helpers (sm_103a; ptxas never auto-fuses these from C++)
// ---------------------------------------------------------------------------
__device__ __forceinline__ unsigned long long ffma2(unsigned long long a,
                                                    unsigned long long b,
                                                    unsigned long long c) {
    unsigned long long d;
    asm("fma.rn.f32x2 %0, %1, %2, %3;" : "=l"(d) : "l"(a), "l"(b), "l"(c));
    return d;
}
__device__ __forceinline__ unsigned long long pack2(float lo, float hi) {
    unsigned long long r;
    asm("mov.b64 %0, {%1, %2};" : "=l"(r) : "f"(lo), "f"(hi));
    return r;
}
__device__ __forceinline__ float2 unpack2(unsigned long long a) {
    float2 r;
    asm("mov.b64 {%0, %1}, %2;" : "=f"(r.x), "=f"(r.y) : "l"(a));
    return r;
}

// ---------------------------------------------------------------------------
// Kernel 1: zero scratch + detect edge_index dtype (int64 -> odd words all 0)
// ---------------------------------------------------------------------------
__global__ void zero_kernel(const int* __restrict__ ei32) {
    if (blockIdx.x == 0 && threadIdx.x == 0) {
        int nz_odd = 0;
        for (int k = 0; k < 128; k++) nz_odd += (ei32[2 * k + 1] != 0);
        g_idx64 = (nz_odd == 0) ? 1 : 0;
    }
    const int stride = gridDim.x * blockDim.x;
    int t = blockIdx.x * blockDim.x + threadIdx.x;
    float4* agg4 = reinterpret_cast<float4*>(g_agg);
    const int total4 = N_NODES * DIM / 4;
    for (int i = t; i < total4; i += stride)
        agg4[i] = make_float4(0.f, 0.f, 0.f, 0.f);
    for (int i = t; i < N_NODES; i += stride)
        g_deg[i] = 0.f;
}

// ---------------------------------------------------------------------------
// Kernel 2: edge scatter. 16 threads/edge, vector reduction atomics.
// ---------------------------------------------------------------------------
__global__ void edge_kernel(const float* __restrict__ x,
                            const void* __restrict__ ei_raw) {
    long long t = (long long)blockIdx.x * blockDim.x + threadIdx.x;
    int e = (int)(t >> 4);
    int c = (int)(t & 15);
    if (e >= N_EDGES) return;

    long long i, j;
    if (g_idx64) {
        const long long* ei = (const long long*)ei_raw;
        i = ei[e];
        j = ei[N_EDGES + e];
    } else {
        const int* ei = (const int*)ei_raw;
        i = ei[e];
        j = ei[N_EDGES + e];
    }

    const float4* xr = reinterpret_cast<const float4*>(x + j * DIM);
    float4 v = xr[c];
    float* dst = g_agg + i * DIM + c * 4;
    asm volatile("red.global.add.v4.f32 [%0], {%1, %2, %3, %4};"
                 :: "l"(dst), "f"(v.x), "f"(v.y), "f"(v.z), "f"(v.w)
                 : "memory");
    if (c == 0) {
        atomicAdd(g_deg + i, 1.0f);
    }
}

// ---------------------------------------------------------------------------
// Kernel 3: register-blocked GEMM + ReLU + LayerNorm.
// CTA: 256 threads, 128 nodes. Thread: 16 nodes x 2 cols (c0=lane, c1=lane+32),
// k-dimension packed into f32x2 halves (summed at the end).
// ---------------------------------------------------------------------------
#define TM 16
#define NODES_PER_CTA 128
#define WPAD 132   // 132*4 B = 528 B row stride: 16B-aligned, conflict-free LDS.128

__global__ __launch_bounds__(256, 2)
void node_kernel(const float* __restrict__ x,
                 const float* __restrict__ W,      // [64][128]
                 const float* __restrict__ bias,   // [64]
                 const float* __restrict__ gamma,  // [64]
                 const float* __restrict__ beta,   // [64]
                 float* __restrict__ out) {
    extern __shared__ float sm[];
    float* Wsh   = sm;                       // [64][WPAD]
    float* insh  = sm + 64 * WPAD;           // [128][128]
    float* shinv = insh + NODES_PER_CTA * 128; // [128]

    const int tid  = threadIdx.x;
    const int base = blockIdx.x * NODES_PER_CTA;

    // Stage W (coalesced global read, row-padded shared write)
    for (int i = tid; i < 64 * 32; i += 256) {
        int c = i >> 5, kq = i & 31;
        *reinterpret_cast<float4*>(&Wsh[c * WPAD + kq * 4]) =
            reinterpret_cast<const float4*>(W)[i];
    }
    // Stage inverse degrees
    if (tid < NODES_PER_CTA) {
        int gn = base + tid;
        if (gn >= N_NODES) gn = N_NODES - 1;
        shinv[tid] = 1.0f / fmaxf(g_deg[gn], 1.0f);
    }
    __syncthreads();

    // Stage concat inputs: insh[n][0:64]=x[n], insh[n][64:128]=agg[n]*inv
    for (int i = tid; i < NODES_PER_CTA * 32; i += 256) {
        int n = i >> 5, kq = i & 31;
        int gn = base + n;
        if (gn >= N_NODES) gn = N_NODES - 1;   // clamp (harmless, deterministic)
        float4 v;
        if (kq < 16) {
            v = reinterpret_cast<const float4*>(x + (size_t)gn * DIM)[kq];
        } else {
            v = reinterpret_cast<const float4*>(g_agg + (size_t)gn * DIM)[kq - 16];
            float inv = shinv[n];
            v.x *= inv; v.y *= inv; v.z *= inv; v.w *= inv;
        }
        *reinterpret_cast<float4*>(&insh[n * 128 + kq * 4]) = v;
    }
    __syncthreads();

    const int tc = tid & 31;
    const int tr = tid >> 5;
    const int c0 = tc, c1 = tc + 32;

    unsigned long long acc0[TM], acc1[TM];
    {
        unsigned long long b0 = pack2(bias[c0], 0.f);
        unsigned long long b1 = pack2(bias[c1], 0.f);
        #pragma unroll
        for (int m = 0; m < TM; m++) { acc0[m] = b0; acc1[m] = b1; }
    }

    const float* w0p = Wsh + c0 * WPAD;
    const float* w1p = Wsh + c1 * WPAD;
    const float* ip  = insh + tr * TM * 128;

    #pragma unroll 4
    for (int kq = 0; kq < 32; kq++) {
        ulonglong2 wa = *reinterpret_cast<const ulonglong2*>(w0p + kq * 4);
        ulonglong2 wb = *reinterpret_cast<const ulonglong2*>(w1p + kq * 4);
        #pragma unroll
        for (int m = 0; m < TM; m++) {
            ulonglong2 iv = *reinterpret_cast<const ulonglong2*>(ip + m * 128 + kq * 4);
            acc0[m] = ffma2(iv.x, wa.x, acc0[m]);
            acc0[m] = ffma2(iv.y, wa.y, acc0[m]);
            acc1[m] = ffma2(iv.x, wb.x, acc1[m]);
            acc1[m] = ffma2(iv.y, wb.y, acc1[m]);
        }
    }

    // Epilogue: sum packed halves, ReLU, warp-wide LayerNorm (warp owns all 64
    // cols of its 16 nodes), scale/shift, store.
    float h0[TM], h1[TM], sv[TM], qv[TM];
    #pragma unroll
    for (int m = 0; m < TM; m++) {
        float2 a = unpack2(acc0[m]);
        float2 b = unpack2(acc1[m]);
        h0[m] = fmaxf(a.x + a.y, 0.f);
        h1[m] = fmaxf(b.x + b.y, 0.f);
        sv[m] = h0[m] + h1[m];
        qv[m] = h0[m] * h0[m] + h1[m] * h1[m];
    }
    #pragma unroll
    for (int off = 16; off > 0; off >>= 1) {
        #pragma unroll
        for (int m = 0; m < TM; m++) {
            sv[m] += __shfl_xor_sync(0xFFFFFFFFu, sv[m], off);
            qv[m] += __shfl_xor_sync(0xFFFFFFFFu, qv[m], off);
        }
    }
    const float ga0 = gamma[c0], ga1 = gamma[c1];
    const float be0 = beta[c0],  be1 = beta[c1];
    #pragma unroll
    for (int m = 0; m < TM; m++) {
        int gn = base + tr * TM + m;
        if (gn < N_NODES) {
            float mu   = sv[m] * (1.0f / DIM);
            float var  = qv[m] * (1.0f / DIM) - mu * mu;
            float rstd = rsqrtf(var + 1e-5f);
            out[(size_t)gn * DIM + c0] = (h0[m] - mu) * rstd * ga0 + be0;
            out[(size_t)gn * DIM + c1] = (h1[m] - mu) * rstd * ga1 + be1;
        }
    }
}

// ---------------------------------------------------------------------------
extern "C" void kernel_launch(void* const* d_in, const int* in_sizes, int n_in,
                              void* d_out, int out_size) {
    const float* x     = (const float*)d_in[0];   // [100000, 64]
    const float* W     = (const float*)d_in[1];   // [64, 128]
    const float* bias  = (const float*)d_in[2];   // [64]
    const float* gamma = (const float*)d_in[3];   // [64]
    const float* beta  = (const float*)d_in[4];   // [64]
    const void*  ei    = d_in[5];                 // [2, 1200000] int32 or int64
    float* out         = (float*)d_out;

    // 1) zero scratch + dtype detect
    zero_kernel<<<2048, 256>>>((const int*)ei);

    // 2) edge scatter: 16 threads per edge
    {
        long long threads = (long long)N_EDGES * 16;
        int blocks = (int)((threads + 255) / 256);
        edge_kernel<<<blocks, 256>>>(x, ei);
    }

    // 3) node phase: register-blocked GEMM + LN
    {
        int smem = (64 * WPAD + NODES_PER_CTA * 128 + NODES_PER_CTA) * sizeof(float);
        cudaFuncSetAttribute(node_kernel,
                             cudaFuncAttributeMaxDynamicSharedMemorySize, smem);
        int blocks = (N_NODES + NODES_PER_CTA - 1) / NODES_PER_CTA;  // 782
        node_kernel<<<blocks, 256, smem>>>(x, W, bias, gamma, beta, out);
    }
}